// round 2
// baseline (speedup 1.0000x reference)
#include <cuda_runtime.h>
#include <math.h>
#include <float.h>

// ---------------- problem constants ----------------
#define DIM 1024
constexpr int B_ = 8, S_ = 512, L_ = 4;
constexpr int M_ = B_ * S_;          // 4096 rows
constexpr int V_ = 32000;
constexpr int STEPS = 8;
constexpr float LR = 0.1f;

constexpr int NROWS  = B_ * (S_ - 1); // 4088 CE rows
constexpr int NSPLIT = 10;            // vocab splits (32000/10 = 3200 = 25*128)
constexpr int VSPLIT = V_ / NSPLIT;
constexpr int NPCB = 256;             // pc-loss partial blocks
constexpr int NCEB = 16;              // ce partial blocks

// ---------------- device scratch (allocation-free rule) ----------------
__device__ float g_x[M_ * DIM];                 // 16 MB embedded input
__device__ float g_states[L_ * M_ * DIM];       // 64 MB
__device__ float g_eps[L_ * M_ * DIM];          // 64 MB
__device__ float g_pm[NROWS * NSPLIT];
__device__ float g_ps[NROWS * NSPLIT];
__device__ float g_pt[NROWS * NSPLIT];
__device__ double g_pc_part[NPCB];
__device__ double g_ce_part[NCEB];

// ---------------- embedding gather: x = emb[input_ids] ----------------
__global__ void gather_kernel(const int* __restrict__ ids,
                              const float* __restrict__ emb) {
    int row = blockIdx.x;                       // 4096
    int id  = ids[row];
    const float4* src = reinterpret_cast<const float4*>(emb + (size_t)id * DIM);
    float4* dst = reinterpret_cast<float4*>(g_x + (size_t)row * DIM);
    dst[threadIdx.x] = src[threadIdx.x];        // 256 threads * float4 = 1024 floats
}

// ---------------- states <- states_init ----------------
__global__ void copy_states_kernel(const float* __restrict__ si) {
    int idx = blockIdx.x * blockDim.x + threadIdx.x;   // over L*M*DIM/4 float4
    reinterpret_cast<float4*>(g_states)[idx] =
        reinterpret_cast<const float4*>(si)[idx];
}

// ---------------- fused SGEMM ----------------
// MODE 0 (eps):    eps_k = mu_k - states_k @ W_k^T - b_k        (NT gemm)
// MODE 1 (update): states_k += 0.1*(eps_k @ W_k) - 0.1*eps_{k+1} (NN gemm)
template<int MODE>
__global__ __launch_bounds__(256, 2)
void gemm_kernel(int k, const float* __restrict__ Wst, const float* __restrict__ bst) {
    constexpr int BM = 128, BN = 128, BK = 16;
    __shared__ float As[BK][BM];
    __shared__ float Bs[BK][BN];

    const int t  = threadIdx.x;
    const int m0 = blockIdx.y * BM;
    const int n0 = blockIdx.x * BN;
    const int tx = t & 15, ty = t >> 4;

    const float* A  = (MODE == 0) ? (g_states + k * (M_ * DIM))
                                  : (g_eps    + k * (M_ * DIM));
    const float* Bp = Wst + k * (DIM * DIM);

    float acc[8][8];
    #pragma unroll
    for (int i = 0; i < 8; i++)
        #pragma unroll
        for (int j = 0; j < 8; j++) acc[i][j] = 0.f;

    for (int k0 = 0; k0 < DIM; k0 += BK) {
        // A tile: 128 rows x 16 k, K-contiguous
        #pragma unroll
        for (int rep = 0; rep < 2; rep++) {
            int idx = t + rep * 256;
            int row = idx >> 2, kq = (idx & 3) << 2;
            float4 v = *reinterpret_cast<const float4*>(&A[(m0 + row) * DIM + k0 + kq]);
            As[kq + 0][row] = v.x; As[kq + 1][row] = v.y;
            As[kq + 2][row] = v.z; As[kq + 3][row] = v.w;
        }
        if (MODE == 0) {
            // NT: Bs[kk][n] = W[(n0+n)*DIM + k0+kk]
            #pragma unroll
            for (int rep = 0; rep < 2; rep++) {
                int idx = t + rep * 256;
                int row = idx >> 2, kq = (idx & 3) << 2;
                float4 v = *reinterpret_cast<const float4*>(&Bp[(n0 + row) * DIM + k0 + kq]);
                Bs[kq + 0][row] = v.x; Bs[kq + 1][row] = v.y;
                Bs[kq + 2][row] = v.z; Bs[kq + 3][row] = v.w;
            }
        } else {
            // NN: Bs[kk][n] = W[(k0+kk)*DIM + n0+n]
            #pragma unroll
            for (int rep = 0; rep < 2; rep++) {
                int idx = t + rep * 256;
                int kr = idx >> 5, nq = (idx & 31) << 2;
                float4 v = *reinterpret_cast<const float4*>(&Bp[(k0 + kr) * DIM + n0 + nq]);
                *reinterpret_cast<float4*>(&Bs[kr][nq]) = v;
            }
        }
        __syncthreads();
        #pragma unroll
        for (int kk = 0; kk < BK; kk++) {
            float a[8], b[8];
            *reinterpret_cast<float4*>(&a[0]) = *reinterpret_cast<const float4*>(&As[kk][ty * 8]);
            *reinterpret_cast<float4*>(&a[4]) = *reinterpret_cast<const float4*>(&As[kk][ty * 8 + 4]);
            *reinterpret_cast<float4*>(&b[0]) = *reinterpret_cast<const float4*>(&Bs[kk][tx * 8]);
            *reinterpret_cast<float4*>(&b[4]) = *reinterpret_cast<const float4*>(&Bs[kk][tx * 8 + 4]);
            #pragma unroll
            for (int i = 0; i < 8; i++)
                #pragma unroll
                for (int j = 0; j < 8; j++) acc[i][j] += a[i] * b[j];
        }
        __syncthreads();
    }

    if (MODE == 0) {
        const float* mu   = (k == 0) ? g_x : g_states + (k - 1) * (M_ * DIM);
        const float* bias = bst + k * DIM;
        float* out = g_eps + k * (M_ * DIM);
        #pragma unroll
        for (int i = 0; i < 8; i++) {
            int m = m0 + ty * 8 + i;
            #pragma unroll
            for (int jq = 0; jq < 8; jq += 4) {
                int n = n0 + tx * 8 + jq;
                float4 mv = *reinterpret_cast<const float4*>(&mu[m * DIM + n]);
                float4 bv = *reinterpret_cast<const float4*>(&bias[n]);
                float4 o;
                o.x = mv.x - acc[i][jq + 0] - bv.x;
                o.y = mv.y - acc[i][jq + 1] - bv.y;
                o.z = mv.z - acc[i][jq + 2] - bv.z;
                o.w = mv.w - acc[i][jq + 3] - bv.w;
                *reinterpret_cast<float4*>(&out[m * DIM + n]) = o;
            }
        }
    } else {
        float* out = g_states + k * (M_ * DIM);
        const bool has_en = (k < L_ - 1);
        const float* en = g_eps + (k + 1) * (M_ * DIM);
        #pragma unroll
        for (int i = 0; i < 8; i++) {
            int m = m0 + ty * 8 + i;
            #pragma unroll
            for (int jq = 0; jq < 8; jq += 4) {
                int n = n0 + tx * 8 + jq;
                float4 sv = *reinterpret_cast<const float4*>(&out[m * DIM + n]);
                float4 ev = has_en ? *reinterpret_cast<const float4*>(&en[m * DIM + n])
                                   : make_float4(0.f, 0.f, 0.f, 0.f);
                float4 o;
                o.x = sv.x + LR * acc[i][jq + 0] - LR * ev.x;
                o.y = sv.y + LR * acc[i][jq + 1] - LR * ev.y;
                o.z = sv.z + LR * acc[i][jq + 2] - LR * ev.z;
                o.w = sv.w + LR * acc[i][jq + 3] - LR * ev.w;
                *reinterpret_cast<float4*>(&out[m * DIM + n]) = o;
            }
        }
    }
}

// ---------------- pc loss: sum of squares over all eps ----------------
__global__ void pc_reduce_kernel() {
    __shared__ double sm[256];
    const int total4 = (L_ * M_ * DIM) / 4;
    double local = 0.0;
    const float4* e4 = reinterpret_cast<const float4*>(g_eps);
    for (int i = blockIdx.x * blockDim.x + threadIdx.x; i < total4;
         i += gridDim.x * blockDim.x) {
        float4 v = e4[i];
        local += (double)v.x * v.x + (double)v.y * v.y +
                 (double)v.z * v.z + (double)v.w * v.w;
    }
    sm[threadIdx.x] = local;
    __syncthreads();
    for (int s = 128; s > 0; s >>= 1) {
        if (threadIdx.x < s) sm[threadIdx.x] += sm[threadIdx.x + s];
        __syncthreads();
    }
    if (threadIdx.x == 0) g_pc_part[blockIdx.x] = sm[0];
}

// ---------------- CE: fused logits GEMM + online softmax ----------------
// grid (NSPLIT, ceil(NROWS/64)); per block: 64 rows x its 3200-vocab split.
__global__ __launch_bounds__(256, 2)
void ce_main_kernel(const int* __restrict__ targets,
                    const float* __restrict__ outW,
                    const float* __restrict__ outB) {
    constexpr int CM = 64, CN = 128, CK = 16;
    __shared__ float As[CK][CM];
    __shared__ float Ws[CK][CN];
    __shared__ int rowoff[CM];
    __shared__ int rowtgt[CM];

    const int split = blockIdx.x;
    const int m0 = blockIdx.y * CM;
    const int t = threadIdx.x;
    const int tx = t & 15, ty = t >> 4;

    if (t < CM) {
        int rg = m0 + t;
        if (rg < NROWS) {
            int b = rg / (S_ - 1), s = rg % (S_ - 1);
            rowoff[t] = (b * S_ + s) * DIM;
            rowtgt[t] = targets[b * S_ + s + 1];
        } else { rowoff[t] = 0; rowtgt[t] = -1; }  // safe in-bounds dummy row
    }
    __syncthreads();

    const float* S3 = g_states + (L_ - 1) * (M_ * DIM);

    float runm[4], runs[4], runt[4];
    #pragma unroll
    for (int i = 0; i < 4; i++) { runm[i] = -1e30f; runs[i] = 0.f; runt[i] = -1e30f; }

    for (int vt = 0; vt < VSPLIT / CN; vt++) {
        const int n0 = split * VSPLIT + vt * CN;
        float acc[4][8];
        #pragma unroll
        for (int i = 0; i < 4; i++)
            #pragma unroll
            for (int j = 0; j < 8; j++) acc[i][j] = 0.f;

        for (int k0 = 0; k0 < DIM; k0 += CK) {
            { // A: 64 rows x 16 k -> 256 float4, one per thread
                int row = t >> 2, kq = (t & 3) << 2;
                int ro = rowoff[row];
                float4 v = *reinterpret_cast<const float4*>(&S3[ro + k0 + kq]);
                As[kq + 0][row] = v.x; As[kq + 1][row] = v.y;
                As[kq + 2][row] = v.z; As[kq + 3][row] = v.w;
            }
            #pragma unroll
            for (int rep = 0; rep < 2; rep++) { // W: 128 vocab x 16 k
                int idx = t + rep * 256;
                int vr = idx >> 2, kq = (idx & 3) << 2;
                float4 v = *reinterpret_cast<const float4*>(&outW[(n0 + vr) * DIM + k0 + kq]);
                Ws[kq + 0][vr] = v.x; Ws[kq + 1][vr] = v.y;
                Ws[kq + 2][vr] = v.z; Ws[kq + 3][vr] = v.w;
            }
            __syncthreads();
            #pragma unroll
            for (int kk = 0; kk < CK; kk++) {
                float a[4], b[8];
                *reinterpret_cast<float4*>(&a[0]) = *reinterpret_cast<const float4*>(&As[kk][ty * 4]);
                *reinterpret_cast<float4*>(&b[0]) = *reinterpret_cast<const float4*>(&Ws[kk][tx * 8]);
                *reinterpret_cast<float4*>(&b[4]) = *reinterpret_cast<const float4*>(&Ws[kk][tx * 8 + 4]);
                #pragma unroll
                for (int i = 0; i < 4; i++)
                    #pragma unroll
                    for (int j = 0; j < 8; j++) acc[i][j] += a[i] * b[j];
            }
            __syncthreads();
        }

        // online softmax update (dummy rows have rowtgt == -1; they update
        // local state but never write out, so correctness is unaffected)
        #pragma unroll
        for (int i = 0; i < 4; i++) {
            float l[8], tmax = -1e30f;
            #pragma unroll
            for (int j = 0; j < 8; j++) {
                l[j] = acc[i][j] + outB[n0 + tx * 8 + j];
                tmax = fmaxf(tmax, l[j]);
            }
            float nm = fmaxf(runm[i], tmax);
            float add = 0.f;
            #pragma unroll
            for (int j = 0; j < 8; j++) add += __expf(l[j] - nm);
            runs[i] = runs[i] * __expf(runm[i] - nm) + add;
            runm[i] = nm;
            int tg = rowtgt[ty * 4 + i];
            #pragma unroll
            for (int j = 0; j < 8; j++)
                if (n0 + tx * 8 + j == tg) runt[i] = l[j];
        }
    }

    // reduce across the 16 tx lanes (xor stays within 16-lane halves of a warp)
    #pragma unroll
    for (int i = 0; i < 4; i++) {
        float m = runm[i], sv = runs[i], tv = runt[i];
        #pragma unroll
        for (int off = 8; off >= 1; off >>= 1) {
            float om = __shfl_xor_sync(0xffffffff, m, off);
            float os = __shfl_xor_sync(0xffffffff, sv, off);
            float ot = __shfl_xor_sync(0xffffffff, tv, off);
            float nm = fmaxf(m, om);
            sv = sv * __expf(m - nm) + os * __expf(om - nm);
            m = nm;
            tv = fmaxf(tv, ot);
        }
        if (tx == 0) {
            int rg = m0 + ty * 4 + i;
            if (rg < NROWS) {
                g_pm[rg * NSPLIT + split] = m;
                g_ps[rg * NSPLIT + split] = sv;
                g_pt[rg * NSPLIT + split] = tv;
            }
        }
    }
}

__global__ void ce_combine_kernel() {
    __shared__ double sm[256];
    double local = 0.0;
    for (int r = blockIdx.x * blockDim.x + threadIdx.x; r < NROWS;
         r += gridDim.x * blockDim.x) {
        float M = -1e30f;
        #pragma unroll
        for (int sp = 0; sp < NSPLIT; sp++) M = fmaxf(M, g_pm[r * NSPLIT + sp]);
        float Z = 0.f;
        #pragma unroll
        for (int sp = 0; sp < NSPLIT; sp++)
            Z += g_ps[r * NSPLIT + sp] * __expf(g_pm[r * NSPLIT + sp] - M);
        float tl = -1e30f;
        #pragma unroll
        for (int sp = 0; sp < NSPLIT; sp++) tl = fmaxf(tl, g_pt[r * NSPLIT + sp]);
        local += (double)M + log((double)Z) - (double)tl;
    }
    sm[threadIdx.x] = local;
    __syncthreads();
    for (int s = 128; s > 0; s >>= 1) {
        if (threadIdx.x < s) sm[threadIdx.x] += sm[threadIdx.x + s];
        __syncthreads();
    }
    if (threadIdx.x == 0) g_ce_part[blockIdx.x] = sm[0];
}

__global__ void finalize_kernel(float* out) {
    double pc = 0.0, ce = 0.0;
    for (int i = 0; i < NPCB; i++) pc += g_pc_part[i];
    for (int i = 0; i < NCEB; i++) ce += g_ce_part[i];
    out[0] = (float)(ce / (double)NROWS);
    out[1] = (float)(pc / ((double)L_ * M_ * DIM));
}

// ---------------- launch ----------------
extern "C" void kernel_launch(void* const* d_in, const int* in_sizes, int n_in,
                              void* d_out, int out_size) {
    const int*   input_ids   = (const int*)d_in[0];
    const int*   targets     = (const int*)d_in[1];
    const float* emb         = (const float*)d_in[2];
    const float* W_stack     = (const float*)d_in[3];
    const float* b_stack     = (const float*)d_in[4];
    const float* out_W       = (const float*)d_in[5];
    const float* out_b       = (const float*)d_in[6];
    const float* states_init = (const float*)d_in[7];
    float* out = (float*)d_out;

    // init scratch
    copy_states_kernel<<<(L_ * M_ * DIM / 4 + 255) / 256, 256>>>(states_init);
    gather_kernel<<<M_, 256>>>(input_ids, emb);

    dim3 ggrid(DIM / 128, M_ / 128); // (8, 32)
    for (int step = 0; step < STEPS; step++) {
        for (int k = 0; k < L_; k++)
            gemm_kernel<0><<<ggrid, 256>>>(k, W_stack, b_stack);
        for (int k = 0; k < L_; k++)
            gemm_kernel<1><<<ggrid, 256>>>(k, W_stack, b_stack);
    }
    // final eps for pc loss
    for (int k = 0; k < L_; k++)
        gemm_kernel<0><<<ggrid, 256>>>(k, W_stack, b_stack);

    pc_reduce_kernel<<<NPCB, 256>>>();

    dim3 cegrid(NSPLIT, (NROWS + 63) / 64); // (10, 64)
    ce_main_kernel<<<cegrid, 256>>>(targets, out_W, out_b);
    ce_combine_kernel<<<NCEB, 256>>>();
    finalize_kernel<<<1, 1>>>(out);
}